// round 13
// baseline (speedup 1.0000x reference)
#include <cuda_runtime.h>
#include <cuda_fp16.h>

#define NUP1    100001            // NUM_USERS + 1
#define NROWS   200001            // total nodes
#define NNZE    2000000
#define NNZ_CAP 2200192           // nnz + <=1 pad/row, rounded
#define NH2     (NROWS * 32)      // 32 x half2 per node = 64 scalars
#define SCAN_B  1024
#define NB      ((NROWS + SCAN_B - 1) / SCAN_B)   // 196

// ---- static device scratch ----
__device__ unsigned g_A16[NH2];   // layer 0 fp16 (half2 per lane)
__device__ unsigned g_B16[NH2];   // layer 1 fp16
__device__ unsigned g_C16[NH2];   // layer 2 fp16

__device__ int   g_cnt[NROWS];    // zero at entry; scan self-clears
__device__ int   g_rank[NNZE];    // per-edge rank within its row
__device__ int   g_ptr[NROWS + 1];
__device__ uint4 g_edgepair[NNZ_CAP / 2];  // 2 edges per uint4, 16B aligned
__device__ volatile unsigned long long g_look[NB];  // cleared by scatter

__device__ __forceinline__ unsigned pack_h2(float2 a) {
    __half2 h = __floats2half2_rn(a.x, a.y);
    return *(unsigned*)&h;
}
__device__ __forceinline__ float2 unpack_h2(unsigned u) {
    return __half22float2(*(__half2*)&u);
}

// init fp16 mirror of embeddings AND histogram+rank (fused).
__global__ void init_kernel(const float2* __restrict__ user2,
                            const float2* __restrict__ item2,
                            const int* __restrict__ rows, int nnz) {
    int i = blockIdx.x * blockDim.x + threadIdx.x;
    if (i < nnz) g_rank[i] = atomicAdd(&g_cnt[rows[i]], 1);
    if (i >= NH2) return;
    float2 v = (i < NUP1 * 32) ? __ldg(&user2[i])
                               : __ldg(&item2[i - NUP1 * 32 + 32]);
    g_A16[i] = pack_h2(v);
}

// Single-pass decoupled-lookback scan over EVEN-PADDED counts -> g_ptr.
__global__ void scan_kernel() {
    int t = threadIdx.x, b = blockIdx.x;
    int lane = t & 31, wid = t >> 5;
    int gid = b * SCAN_B + t;

    int cnt = (gid < NROWS) ? g_cnt[gid] : 0;
    int pc  = (cnt + 1) & ~1;                 // pad to even (16B alignment)

    int incl = pc;
    #pragma unroll
    for (int o = 1; o < 32; o <<= 1) {
        int n = __shfl_up_sync(0xffffffffu, incl, o);
        if (lane >= o) incl += n;
    }
    __shared__ int wsum[32];
    __shared__ int s_excl;
    if (lane == 31) wsum[wid] = incl;
    __syncthreads();
    if (wid == 0) {
        int v = wsum[lane];
        #pragma unroll
        for (int o = 1; o < 32; o <<= 1) {
            int n = __shfl_up_sync(0xffffffffu, v, o);
            if (lane >= o) v += n;
        }
        wsum[lane] = v;
    }
    __syncthreads();
    int block_incl = incl + (wid ? wsum[wid - 1] : 0);
    int total = wsum[31];

    if (t == 0) {
        if (b == 0) { g_look[0] = (2ull << 32) | (unsigned)total; s_excl = 0; }
        else          g_look[b] = (1ull << 32) | (unsigned)total;
    }
    if (b > 0 && wid == 0) {
        int excl = 0;
        int idx = b - 1;
        while (true) {
            int look = idx - lane;
            unsigned long long w; int st;
            do {
                w = g_look[look < 0 ? 0 : look];
                st = (look < 0) ? 2 : (int)(w >> 32);
            } while (__any_sync(0xffffffffu, st == 0));
            int val = (look < 0) ? 0 : (int)(unsigned)w;
            unsigned pm = __ballot_sync(0xffffffffu, (look >= 0) && st == 2);
            int contrib;
            if (pm) {
                int plane = __ffs(pm) - 1;
                contrib = (lane <= plane) ? val : 0;
            } else {
                contrib = val;
            }
            #pragma unroll
            for (int o = 16; o; o >>= 1)
                contrib += __shfl_down_sync(0xffffffffu, contrib, o);
            contrib = __shfl_sync(0xffffffffu, contrib, 0);
            excl += contrib;
            if (pm) break;
            idx -= 32;
        }
        if (lane == 0) {
            g_look[b] = (2ull << 32) | (unsigned)(excl + total);
            s_excl = excl;
        }
    }
    __syncthreads();
    if (gid < NROWS) {
        int ex = s_excl + block_incl - pc;
        g_ptr[gid] = ex;
        g_cnt[gid] = 0;                        // self-clean for next replay
        if (gid == NROWS - 1) g_ptr[NROWS] = ex + pc;
    }
}

// Atomic-free bucket: pos = ptr[row] + rank. Pad slots stay (0,0) forever
// (static zero-init, never written -> v=0, col=0: harmless). Clears g_look.
__global__ void scatter_kernel(const int* __restrict__ rows,
                               const int* __restrict__ cols,
                               const float* __restrict__ vals, int nnz) {
    int e = blockIdx.x * blockDim.x + threadIdx.x;
    if (e < NB) g_look[e] = 0ull;
    if (e >= nnz) return;
    int pos = g_ptr[rows[e]] + g_rank[e];
    uint2* edges = (uint2*)g_edgepair;
    edges[pos] = make_uint2((unsigned)cols[e], (unsigned)__float_as_int(vals[e]));
}

// One warp per row: 32 lanes x half2 (4B) = one 128B row.
// Edge pairs load as single LDG.128 (rows even-padded -> 16B aligned).
__device__ __forceinline__ float2 row_spmv(const unsigned* __restrict__ xl,
                                           int s, int e) {
    float2 acc = make_float2(0.f, 0.f);
    for (int j = s; j < e; j += 4) {
        uint4 E0 = __ldg(&g_edgepair[(unsigned)j >> 1]);          // edges j, j+1
        uint4 E1 = (j + 2 < e) ? __ldg(&g_edgepair[((unsigned)j >> 1) + 1])
                               : make_uint4(0u, 0u, 0u, 0u);      // edges j+2, j+3
        unsigned h0 = __ldg(&xl[E0.x * 32u]);
        unsigned h1 = __ldg(&xl[E0.z * 32u]);
        unsigned h2 = __ldg(&xl[E1.x * 32u]);
        unsigned h3 = __ldg(&xl[E1.z * 32u]);
        float v0 = __uint_as_float(E0.y);
        float v1 = __uint_as_float(E0.w);
        float v2 = __uint_as_float(E1.y);
        float v3 = __uint_as_float(E1.w);
        float2 a;
        a = unpack_h2(h0);
        acc.x = fmaf(v0, a.x, acc.x); acc.y = fmaf(v0, a.y, acc.y);
        a = unpack_h2(h1);
        acc.x = fmaf(v1, a.x, acc.x); acc.y = fmaf(v1, a.y, acc.y);
        a = unpack_h2(h2);
        acc.x = fmaf(v2, a.x, acc.x); acc.y = fmaf(v2, a.y, acc.y);
        a = unpack_h2(h3);
        acc.x = fmaf(v3, a.x, acc.x); acc.y = fmaf(v3, a.y, acc.y);
    }
    return acc;
}

__global__ void spmm_mid(int layer) {
    int row = (blockIdx.x * blockDim.x + threadIdx.x) >> 5;
    if (row >= NROWS) return;
    int lane = threadIdx.x & 31;
    const unsigned* __restrict__ xl =
        ((layer == 0) ? g_A16 : g_B16) + lane;
    unsigned* __restrict__ y = (layer == 0) ? g_B16 : g_C16;
    float2 s = row_spmv(xl, g_ptr[row], g_ptr[row + 1]);
    y[(unsigned)row * 32 + lane] = pack_h2(s);
}

__global__ void spmm_final(const float2* __restrict__ user2,
                           const float2* __restrict__ item2,
                           float2* __restrict__ out) {
    int row = (blockIdx.x * blockDim.x + threadIdx.x) >> 5;
    if (row >= NROWS) return;
    int lane = threadIdx.x & 31;
    const unsigned* __restrict__ xl = g_C16 + lane;
    float2 s = row_spmv(xl, g_ptr[row], g_ptr[row + 1]);
    unsigned o = (unsigned)row * 32 + lane;
    float2 a = (row < NUP1) ? __ldg(&user2[o])
                            : __ldg(&item2[(unsigned)(row - NUP1 + 1) * 32 + lane]);
    float2 b = unpack_h2(g_B16[o]);
    float2 c = unpack_h2(g_C16[o]);
    int outrow = (row < NUP1) ? row : row + 1;
    out[(size_t)outrow * 32 + lane] =
        make_float2((a.x + b.x + c.x + s.x) * 0.25f,
                    (a.y + b.y + c.y + s.y) * 0.25f);
    if (row == 0)
        out[(size_t)NUP1 * 32 + lane] = make_float2(0.f, 0.f);
}

extern "C" void kernel_launch(void* const* d_in, const int* in_sizes, int n_in,
                              void* d_out, int out_size) {
    const float2* user2 = (const float2*)d_in[0];
    const float2* item2 = (const float2*)d_in[1];
    const int*    rows  = (const int*)d_in[2];
    const int*    cols  = (const int*)d_in[3];
    const float*  vals  = (const float*)d_in[4];
    float2*       out   = (float2*)d_out;

    const int nnz = in_sizes[2];
    const int TB = 256;

    const int gInit = (NH2 + TB - 1) / TB;     // NH2 > NNZE, covers both
    const int gEdge = (nnz + TB - 1) / TB;
    const long long spmmThr = (long long)NROWS * 32;
    const int gSpmm = (int)((spmmThr + TB - 1) / TB);

    init_kernel<<<gInit, TB>>>(user2, item2, rows, nnz);   // 0: init + hist/rank
    scan_kernel<<<NB, SCAN_B>>>();                         // 1
    scatter_kernel<<<gEdge, TB>>>(rows, cols, vals, nnz);  // 2 (atomic-free)
    spmm_mid<<<gSpmm, TB>>>(0);                            // 3
    spmm_mid<<<gSpmm, TB>>>(1);                            // 4
    spmm_final<<<gSpmm, TB>>>(user2, item2, out);          // 5
}

// round 14
// speedup vs baseline: 1.3414x; 1.3414x over previous
#include <cuda_runtime.h>
#include <cuda_fp16.h>

#define NUP1    100001            // NUM_USERS + 1
#define NROWS   200001            // total nodes
#define NNZE    2000000
#define NF4     (NROWS * 16)      // 16 x half4 per node = 64 scalars
#define SCAN_B  1024
#define NB      ((NROWS + SCAN_B - 1) / SCAN_B)   // 196
#define DBINS   64

// ---- static device scratch ----
__device__ uint2  g_A16[NF4];     // layer 0 fp16 (half4 packed)
__device__ uint2  g_B16[NF4];     // layer 1 fp16
__device__ uint2  g_C16[NF4];     // layer 2 fp16

__device__ int   g_cnt[NROWS];    // zero at entry; scan self-clears
__device__ int   g_rank[NNZE];    // per-edge rank within its row
__device__ int   g_ptr[NROWS + 1];
__device__ uint2 g_edge[NNZE];    // (col, fp32 val bits)
__device__ volatile unsigned long long g_look[NB];  // cleared by scatter

__device__ int   g_deg_hist[DBINS];   // zero at entry; deg_scan self-clears
__device__ int   g_deg_fill[DBINS];   // rebuilt by deg_scan each run
__device__ int   g_order[NROWS + 1];  // degree-sorted row ids (+sentinel)

__device__ __forceinline__ uint2 pack_half4(float2 a, float2 b) {
    __half2 h0 = __floats2half2_rn(a.x, a.y);
    __half2 h1 = __floats2half2_rn(b.x, b.y);
    return make_uint2(*(unsigned*)&h0, *(unsigned*)&h1);
}
__device__ __forceinline__ void unpack_half4(uint2 u, float2& a, float2& b) {
    a = __half22float2(*(__half2*)&u.x);
    b = __half22float2(*(__half2*)&u.y);
}

// init fp16 mirror of embeddings AND histogram+rank (fused).
__global__ void init_kernel(const float4* __restrict__ user4,
                            const float4* __restrict__ item4,
                            const int* __restrict__ rows, int nnz) {
    int i = blockIdx.x * blockDim.x + threadIdx.x;
    if (i < nnz) g_rank[i] = atomicAdd(&g_cnt[rows[i]], 1);
    if (i >= NF4) return;
    float4 v = (i < NUP1 * 16) ? __ldg(&user4[i])
                               : __ldg(&item4[i - NUP1 * 16 + 16]);
    g_A16[i] = pack_half4(make_float2(v.x, v.y), make_float2(v.z, v.w));
}

// Single-pass decoupled-lookback scan -> g_ptr; self-clears g_cnt.
// Also accumulates the degree histogram (smem-aggregated).
__global__ void scan_kernel() {
    int t = threadIdx.x, b = blockIdx.x;
    int lane = t & 31, wid = t >> 5;
    int gid = b * SCAN_B + t;

    __shared__ int dh[DBINS];
    if (t < DBINS) dh[t] = 0;

    int cnt = (gid < NROWS) ? g_cnt[gid] : 0;

    int incl = cnt;
    #pragma unroll
    for (int o = 1; o < 32; o <<= 1) {
        int n = __shfl_up_sync(0xffffffffu, incl, o);
        if (lane >= o) incl += n;
    }
    __shared__ int wsum[32];
    __shared__ int s_excl;
    if (lane == 31) wsum[wid] = incl;
    __syncthreads();
    if (wid == 0) {
        int v = wsum[lane];
        #pragma unroll
        for (int o = 1; o < 32; o <<= 1) {
            int n = __shfl_up_sync(0xffffffffu, v, o);
            if (lane >= o) v += n;
        }
        wsum[lane] = v;
    }
    if (gid < NROWS) atomicAdd(&dh[min(cnt, DBINS - 1)], 1);
    __syncthreads();
    int block_incl = incl + (wid ? wsum[wid - 1] : 0);
    int total = wsum[31];

    if (t == 0) {
        if (b == 0) { g_look[0] = (2ull << 32) | (unsigned)total; s_excl = 0; }
        else          g_look[b] = (1ull << 32) | (unsigned)total;
    }
    if (b > 0 && wid == 0) {
        int excl = 0;
        int idx = b - 1;
        while (true) {
            int look = idx - lane;
            unsigned long long w; int st;
            do {
                w = g_look[look < 0 ? 0 : look];
                st = (look < 0) ? 2 : (int)(w >> 32);
            } while (__any_sync(0xffffffffu, st == 0));
            int val = (look < 0) ? 0 : (int)(unsigned)w;
            unsigned pm = __ballot_sync(0xffffffffu, (look >= 0) && st == 2);
            int contrib;
            if (pm) {
                int plane = __ffs(pm) - 1;
                contrib = (lane <= plane) ? val : 0;
            } else {
                contrib = val;
            }
            #pragma unroll
            for (int o = 16; o; o >>= 1)
                contrib += __shfl_down_sync(0xffffffffu, contrib, o);
            contrib = __shfl_sync(0xffffffffu, contrib, 0);
            excl += contrib;
            if (pm) break;
            idx -= 32;
        }
        if (lane == 0) {
            g_look[b] = (2ull << 32) | (unsigned)(excl + total);
            s_excl = excl;
        }
    }
    __syncthreads();
    if (gid < NROWS) {
        int ex = s_excl + block_incl - cnt;
        g_ptr[gid] = ex;
        g_cnt[gid] = 0;                        // self-clean for next replay
        if (gid == NROWS - 1) g_ptr[NROWS] = ex + cnt;
    }
    if (t < DBINS && dh[t]) atomicAdd(&g_deg_hist[t], dh[t]);
}

// Exclusive scan of 64 degree bins -> g_deg_fill; self-cleans hist;
// writes order sentinel.
__global__ void deg_scan_kernel() {
    int t = threadIdx.x;                       // 0..63
    __shared__ int sh[DBINS];
    int v = g_deg_hist[t];
    sh[t] = v;
    __syncthreads();
    for (int o = 1; o < DBINS; o <<= 1) {
        int add = (t >= o) ? sh[t - o] : 0;
        __syncthreads();
        sh[t] += add;
        __syncthreads();
    }
    g_deg_fill[t] = sh[t] - v;                 // exclusive
    g_deg_hist[t] = 0;                         // self-clean for next replay
    if (t == 0) g_order[NROWS] = NROWS;        // sentinel
}

// Atomic-free edge bucket + degree-sorted order fill. Clears g_look.
__global__ void scatter_kernel(const int* __restrict__ rows,
                               const int* __restrict__ cols,
                               const float* __restrict__ vals, int nnz) {
    int e = blockIdx.x * blockDim.x + threadIdx.x;
    if (e < NB) g_look[e] = 0ull;
    if (e < NROWS) {
        int deg = g_ptr[e + 1] - g_ptr[e];
        int pos = atomicAdd(&g_deg_fill[min(deg, DBINS - 1)], 1);
        g_order[pos] = e;
    }
    if (e >= nnz) return;
    int pos = g_ptr[rows[e]] + g_rank[e];
    g_edge[pos] = make_uint2((unsigned)cols[e], (unsigned)__float_as_int(vals[e]));
}

// Half-warp per row: 16 lanes x half4 (8B) = one 128B row.
// fp16 gather, fp32 FFMA accumulation (R12 shape, unchanged).
__device__ __forceinline__ void row_spmv(const uint2* __restrict__ xl,
                                         int s, int e,
                                         float2& s0, float2& s1) {
    s0 = make_float2(0.f, 0.f);
    s1 = make_float2(0.f, 0.f);
    for (int j = s; j < e; j += 4) {
        uint2 e0 = __ldg(&g_edge[j]);
        uint2 e1 = (j + 1 < e) ? __ldg(&g_edge[j + 1]) : make_uint2(0u, 0u);
        uint2 e2 = (j + 2 < e) ? __ldg(&g_edge[j + 2]) : make_uint2(0u, 0u);
        uint2 e3 = (j + 3 < e) ? __ldg(&g_edge[j + 3]) : make_uint2(0u, 0u);
        uint2 g0 = __ldg(&xl[e0.x * 16u]);
        uint2 g1 = __ldg(&xl[e1.x * 16u]);
        uint2 g2 = __ldg(&xl[e2.x * 16u]);
        uint2 g3 = __ldg(&xl[e3.x * 16u]);
        float v0 = __uint_as_float(e0.y);
        float v1 = __uint_as_float(e1.y);
        float v2 = __uint_as_float(e2.y);
        float v3 = __uint_as_float(e3.y);
        float2 a, b;
        unpack_half4(g0, a, b);
        s0.x = fmaf(v0, a.x, s0.x); s0.y = fmaf(v0, a.y, s0.y);
        s1.x = fmaf(v0, b.x, s1.x); s1.y = fmaf(v0, b.y, s1.y);
        unpack_half4(g1, a, b);
        s0.x = fmaf(v1, a.x, s0.x); s0.y = fmaf(v1, a.y, s0.y);
        s1.x = fmaf(v1, b.x, s1.x); s1.y = fmaf(v1, b.y, s1.y);
        unpack_half4(g2, a, b);
        s0.x = fmaf(v2, a.x, s0.x); s0.y = fmaf(v2, a.y, s0.y);
        s1.x = fmaf(v2, b.x, s1.x); s1.y = fmaf(v2, b.y, s1.y);
        unpack_half4(g3, a, b);
        s0.x = fmaf(v3, a.x, s0.x); s0.y = fmaf(v3, a.y, s0.y);
        s1.x = fmaf(v3, b.x, s1.x); s1.y = fmaf(v3, b.y, s1.y);
    }
}

__global__ void __launch_bounds__(256, 8) spmm_mid(int layer) {
    int warp = (blockIdx.x * blockDim.x + threadIdx.x) >> 5;
    int lane = threadIdx.x & 31;
    int slot = warp * 2 + (lane >> 4);
    if (slot >= NROWS) return;
    int row = g_order[slot];                  // degree-sorted pairing
    int l15 = lane & 15;
    const uint2* __restrict__ xl =
        ((layer == 0) ? g_A16 : g_B16) + l15;
    uint2* __restrict__ y = (layer == 0) ? g_B16 : g_C16;
    float2 s0, s1;
    row_spmv(xl, g_ptr[row], g_ptr[row + 1], s0, s1);
    y[(size_t)row * 16 + l15] = pack_half4(s0, s1);
}

__global__ void spmm_final(const float4* __restrict__ user4,
                           const float4* __restrict__ item4,
                           float4* __restrict__ out) {
    int warp = (blockIdx.x * blockDim.x + threadIdx.x) >> 5;
    int lane = threadIdx.x & 31;
    int slot = warp * 2 + (lane >> 4);
    if (slot >= NROWS) return;
    int row = g_order[slot];
    int l15 = lane & 15;
    const uint2* __restrict__ xl = g_C16 + l15;
    float2 s0, s1;
    row_spmv(xl, g_ptr[row], g_ptr[row + 1], s0, s1);
    size_t o = (size_t)row * 16 + l15;
    float4 a = (row < NUP1) ? __ldg(&user4[o])
                            : __ldg(&item4[(size_t)(row - NUP1 + 1) * 16 + l15]);
    float2 b0, b1, c0, c1;
    unpack_half4(g_B16[o], b0, b1);
    unpack_half4(g_C16[o], c0, c1);
    int outrow = (row < NUP1) ? row : row + 1;
    out[(size_t)outrow * 16 + l15] =
        make_float4((a.x + b0.x + c0.x + s0.x) * 0.25f,
                    (a.y + b0.y + c0.y + s0.y) * 0.25f,
                    (a.z + b1.x + c1.x + s1.x) * 0.25f,
                    (a.w + b1.y + c1.y + s1.y) * 0.25f);
    if (row == 0)
        out[(size_t)NUP1 * 16 + l15] = make_float4(0.f, 0.f, 0.f, 0.f);
}

extern "C" void kernel_launch(void* const* d_in, const int* in_sizes, int n_in,
                              void* d_out, int out_size) {
    const float4* user4 = (const float4*)d_in[0];
    const float4* item4 = (const float4*)d_in[1];
    const int*    rows  = (const int*)d_in[2];
    const int*    cols  = (const int*)d_in[3];
    const float*  vals  = (const float*)d_in[4];
    float4*       out   = (float4*)d_out;

    const int nnz = in_sizes[2];
    const int TB = 256;

    const int gInit = (NF4 + TB - 1) / TB;     // NF4 > NNZE, covers both
    const int gEdge = (nnz + TB - 1) / TB;
    const int nWarp = (NROWS + 1) / 2;
    const int gSpmm = (nWarp * 32 + TB - 1) / TB;

    init_kernel<<<gInit, TB>>>(user4, item4, rows, nnz);   // 0
    scan_kernel<<<NB, SCAN_B>>>();                         // 1 (+deg hist)
    deg_scan_kernel<<<1, DBINS>>>();                       // 2
    scatter_kernel<<<gEdge, TB>>>(rows, cols, vals, nnz);  // 3 (+order fill)
    spmm_mid<<<gSpmm, TB>>>(0);                            // 4
    spmm_mid<<<gSpmm, TB>>>(1);                            // 5
    spmm_final<<<gSpmm, TB>>>(user4, item4, out);          // 6
}

// round 15
// speedup vs baseline: 1.5756x; 1.1746x over previous
#include <cuda_runtime.h>
#include <cuda_fp16.h>

#define NUP1    100001            // NUM_USERS + 1
#define NROWS   200001            // total nodes
#define NNZE    2000000
#define NF4     (NROWS * 16)      // 16 x half4 per node = 64 scalars
#define SCAN_B  1024
#define NB      ((NROWS + SCAN_B - 1) / SCAN_B)   // 196

// ---- static device scratch ----
__device__ uint2  g_A16[NF4];     // layer 0 fp16 (half4 packed)
__device__ uint2  g_B16[NF4];     // layer 1 fp16
__device__ uint2  g_C16[NF4];     // layer 2 fp16

__device__ int   g_cnt[NROWS];    // zero at entry; scan self-clears
__device__ int   g_rank[NNZE];    // per-edge rank within its row
__device__ int   g_ptr[NROWS + 1];
__device__ uint2 g_edge[NNZE];    // (col, fp32 val bits)
__device__ volatile unsigned long long g_look[NB];  // cleared by scatter

__device__ __forceinline__ uint2 pack_half4(float2 a, float2 b) {
    __half2 h0 = __floats2half2_rn(a.x, a.y);
    __half2 h1 = __floats2half2_rn(b.x, b.y);
    return make_uint2(*(unsigned*)&h0, *(unsigned*)&h1);
}
__device__ __forceinline__ void unpack_half4(uint2 u, float2& a, float2& b) {
    a = __half22float2(*(__half2*)&u.x);
    b = __half22float2(*(__half2*)&u.y);
}

// fp16 mirror of embeddings (independent of edge preprocessing).
__global__ void mirror_kernel(const float4* __restrict__ user4,
                              const float4* __restrict__ item4) {
    int i = blockIdx.x * blockDim.x + threadIdx.x;
    if (i >= NF4) return;
    float4 v = (i < NUP1 * 16) ? __ldg(&user4[i])
                               : __ldg(&item4[i - NUP1 * 16 + 16]);
    g_A16[i] = pack_half4(make_float2(v.x, v.y), make_float2(v.z, v.w));
}

// histogram + per-edge rank.
__global__ void rank_kernel(const int* __restrict__ rows, int nnz) {
    int i = blockIdx.x * blockDim.x + threadIdx.x;
    if (i < nnz) g_rank[i] = atomicAdd(&g_cnt[rows[i]], 1);
}

// Single-pass decoupled-lookback scan -> g_ptr; self-clears g_cnt.
__global__ void scan_kernel() {
    int t = threadIdx.x, b = blockIdx.x;
    int lane = t & 31, wid = t >> 5;
    int gid = b * SCAN_B + t;

    int cnt = (gid < NROWS) ? g_cnt[gid] : 0;

    int incl = cnt;
    #pragma unroll
    for (int o = 1; o < 32; o <<= 1) {
        int n = __shfl_up_sync(0xffffffffu, incl, o);
        if (lane >= o) incl += n;
    }
    __shared__ int wsum[32];
    __shared__ int s_excl;
    if (lane == 31) wsum[wid] = incl;
    __syncthreads();
    if (wid == 0) {
        int v = wsum[lane];
        #pragma unroll
        for (int o = 1; o < 32; o <<= 1) {
            int n = __shfl_up_sync(0xffffffffu, v, o);
            if (lane >= o) v += n;
        }
        wsum[lane] = v;
    }
    __syncthreads();
    int block_incl = incl + (wid ? wsum[wid - 1] : 0);
    int total = wsum[31];

    if (t == 0) {
        if (b == 0) { g_look[0] = (2ull << 32) | (unsigned)total; s_excl = 0; }
        else          g_look[b] = (1ull << 32) | (unsigned)total;
    }
    if (b > 0 && wid == 0) {
        int excl = 0;
        int idx = b - 1;
        while (true) {
            int look = idx - lane;
            unsigned long long w; int st;
            do {
                w = g_look[look < 0 ? 0 : look];
                st = (look < 0) ? 2 : (int)(w >> 32);
            } while (__any_sync(0xffffffffu, st == 0));
            int val = (look < 0) ? 0 : (int)(unsigned)w;
            unsigned pm = __ballot_sync(0xffffffffu, (look >= 0) && st == 2);
            int contrib;
            if (pm) {
                int plane = __ffs(pm) - 1;
                contrib = (lane <= plane) ? val : 0;
            } else {
                contrib = val;
            }
            #pragma unroll
            for (int o = 16; o; o >>= 1)
                contrib += __shfl_down_sync(0xffffffffu, contrib, o);
            contrib = __shfl_sync(0xffffffffu, contrib, 0);
            excl += contrib;
            if (pm) break;
            idx -= 32;
        }
        if (lane == 0) {
            g_look[b] = (2ull << 32) | (unsigned)(excl + total);
            s_excl = excl;
        }
    }
    __syncthreads();
    if (gid < NROWS) {
        int ex = s_excl + block_incl - cnt;
        g_ptr[gid] = ex;
        g_cnt[gid] = 0;                        // self-clean for next replay
        if (gid == NROWS - 1) g_ptr[NROWS] = ex + cnt;
    }
}

// Atomic-free bucket: pos = ptr[row] + precomputed rank. Clears g_look.
__global__ void scatter_kernel(const int* __restrict__ rows,
                               const int* __restrict__ cols,
                               const float* __restrict__ vals, int nnz) {
    int e = blockIdx.x * blockDim.x + threadIdx.x;
    if (e < NB) g_look[e] = 0ull;
    if (e >= nnz) return;
    int pos = g_ptr[rows[e]] + g_rank[e];
    g_edge[pos] = make_uint2((unsigned)cols[e], (unsigned)__float_as_int(vals[e]));
}

// Half-warp per row: 16 lanes x half4 (8B) = one 128B row.
// fp16 gather, fp32 FFMA accumulation (R12 shape, unchanged).
__device__ __forceinline__ void row_spmv(const uint2* __restrict__ xl,
                                         int s, int e,
                                         float2& s0, float2& s1) {
    s0 = make_float2(0.f, 0.f);
    s1 = make_float2(0.f, 0.f);
    for (int j = s; j < e; j += 4) {
        uint2 e0 = __ldg(&g_edge[j]);
        uint2 e1 = (j + 1 < e) ? __ldg(&g_edge[j + 1]) : make_uint2(0u, 0u);
        uint2 e2 = (j + 2 < e) ? __ldg(&g_edge[j + 2]) : make_uint2(0u, 0u);
        uint2 e3 = (j + 3 < e) ? __ldg(&g_edge[j + 3]) : make_uint2(0u, 0u);
        uint2 g0 = __ldg(&xl[e0.x * 16u]);
        uint2 g1 = __ldg(&xl[e1.x * 16u]);
        uint2 g2 = __ldg(&xl[e2.x * 16u]);
        uint2 g3 = __ldg(&xl[e3.x * 16u]);
        float v0 = __uint_as_float(e0.y);
        float v1 = __uint_as_float(e1.y);
        float v2 = __uint_as_float(e2.y);
        float v3 = __uint_as_float(e3.y);
        float2 a, b;
        unpack_half4(g0, a, b);
        s0.x = fmaf(v0, a.x, s0.x); s0.y = fmaf(v0, a.y, s0.y);
        s1.x = fmaf(v0, b.x, s1.x); s1.y = fmaf(v0, b.y, s1.y);
        unpack_half4(g1, a, b);
        s0.x = fmaf(v1, a.x, s0.x); s0.y = fmaf(v1, a.y, s0.y);
        s1.x = fmaf(v1, b.x, s1.x); s1.y = fmaf(v1, b.y, s1.y);
        unpack_half4(g2, a, b);
        s0.x = fmaf(v2, a.x, s0.x); s0.y = fmaf(v2, a.y, s0.y);
        s1.x = fmaf(v2, b.x, s1.x); s1.y = fmaf(v2, b.y, s1.y);
        unpack_half4(g3, a, b);
        s0.x = fmaf(v3, a.x, s0.x); s0.y = fmaf(v3, a.y, s0.y);
        s1.x = fmaf(v3, b.x, s1.x); s1.y = fmaf(v3, b.y, s1.y);
    }
}

__global__ void spmm_mid(int layer) {
    int warp = (blockIdx.x * blockDim.x + threadIdx.x) >> 5;
    int lane = threadIdx.x & 31;
    int row  = warp * 2 + (lane >> 4);
    if (row >= NROWS) return;
    int l15 = lane & 15;
    const uint2* __restrict__ xl =
        ((layer == 0) ? g_A16 : g_B16) + l15;
    uint2* __restrict__ y = (layer == 0) ? g_B16 : g_C16;
    float2 s0, s1;
    row_spmv(xl, g_ptr[row], g_ptr[row + 1], s0, s1);
    y[(size_t)row * 16 + l15] = pack_half4(s0, s1);
}

__global__ void spmm_final(const float4* __restrict__ user4,
                           const float4* __restrict__ item4,
                           float4* __restrict__ out) {
    int warp = (blockIdx.x * blockDim.x + threadIdx.x) >> 5;
    int lane = threadIdx.x & 31;
    int row  = warp * 2 + (lane >> 4);
    if (row >= NROWS) return;
    int l15 = lane & 15;
    const uint2* __restrict__ xl = g_C16 + l15;
    float2 s0, s1;
    row_spmv(xl, g_ptr[row], g_ptr[row + 1], s0, s1);
    size_t o = (size_t)row * 16 + l15;
    float4 a = (row < NUP1) ? __ldg(&user4[o])
                            : __ldg(&item4[(size_t)(row - NUP1 + 1) * 16 + l15]);
    float2 b0, b1, c0, c1;
    unpack_half4(g_B16[o], b0, b1);
    unpack_half4(g_C16[o], c0, c1);
    int outrow = (row < NUP1) ? row : row + 1;
    out[(size_t)outrow * 16 + l15] =
        make_float4((a.x + b0.x + c0.x + s0.x) * 0.25f,
                    (a.y + b0.y + c0.y + s0.y) * 0.25f,
                    (a.z + b1.x + c1.x + s1.x) * 0.25f,
                    (a.w + b1.y + c1.y + s1.y) * 0.25f);
    if (row == 0)
        out[(size_t)NUP1 * 16 + l15] = make_float4(0.f, 0.f, 0.f, 0.f);
}

extern "C" void kernel_launch(void* const* d_in, const int* in_sizes, int n_in,
                              void* d_out, int out_size) {
    const float4* user4 = (const float4*)d_in[0];
    const float4* item4 = (const float4*)d_in[1];
    const int*    rows  = (const int*)d_in[2];
    const int*    cols  = (const int*)d_in[3];
    const float*  vals  = (const float*)d_in[4];
    float4*       out   = (float4*)d_out;

    const int nnz = in_sizes[2];
    const int TB = 256;

    const int gMir  = (NF4 + TB - 1) / TB;
    const int gEdge = (nnz + TB - 1) / TB;
    const int nWarp = (NROWS + 1) / 2;
    const int gSpmm = (nWarp * 32 + TB - 1) / TB;

    // One-time stream/event resources (host-side only; no device memory).
    static cudaStream_t s2 = nullptr;
    static cudaEvent_t  evFork = nullptr, evJoin = nullptr;
    if (!s2) {
        cudaStreamCreateWithFlags(&s2, cudaStreamNonBlocking);
        cudaEventCreateWithFlags(&evFork, cudaEventDisableTiming);
        cudaEventCreateWithFlags(&evJoin, cudaEventDisableTiming);
    }

    // Fork: mirror (fp16 embedding copy) runs on s2, overlapping the
    // rank -> scan -> scatter chain on the main stream.
    cudaEventRecord(evFork, 0);
    cudaStreamWaitEvent(s2, evFork, 0);
    mirror_kernel<<<gMir, TB, 0, s2>>>(user4, item4);
    cudaEventRecord(evJoin, s2);

    rank_kernel<<<gEdge, TB>>>(rows, nnz);
    scan_kernel<<<NB, SCAN_B>>>();
    scatter_kernel<<<gEdge, TB>>>(rows, cols, vals, nnz);

    // Join: spmm layer 1 needs both the mirror and the CSR.
    cudaStreamWaitEvent(0, evJoin, 0);

    spmm_mid<<<gSpmm, TB>>>(0);
    spmm_mid<<<gSpmm, TB>>>(1);
    spmm_final<<<gSpmm, TB>>>(user4, item4, out);
}

// round 16
// speedup vs baseline: 1.5907x; 1.0096x over previous
#include <cuda_runtime.h>
#include <cuda_fp16.h>

#define NUP1    100001            // NUM_USERS + 1
#define NROWS   200001            // total nodes
#define NNZE    2000000
#define NF4     (NROWS * 16)      // 16 x half4 per node = 64 scalars
#define SCAN_B  1024
#define NB      ((NROWS + SCAN_B - 1) / SCAN_B)   // 196

// ---- static device scratch ----
__device__ uint2  g_A16[NF4];     // layer 0 fp16 (half4 packed)
__device__ uint2  g_B16[NF4];     // layer 1 fp16
__device__ uint2  g_C16[NF4];     // layer 2 fp16

__device__ int   g_cnt[NROWS];    // zero at entry; scan self-clears
__device__ int   g_rank[NNZE];    // per-edge rank within its row
__device__ int   g_ptr[NROWS + 1];
__device__ uint2 g_edge[NNZE];    // (col, fp32 val bits)
__device__ volatile unsigned long long g_look[NB];  // cleared by scatter

__device__ __forceinline__ uint2 pack_half4(float2 a, float2 b) {
    __half2 h0 = __floats2half2_rn(a.x, a.y);
    __half2 h1 = __floats2half2_rn(b.x, b.y);
    return make_uint2(*(unsigned*)&h0, *(unsigned*)&h1);
}
__device__ __forceinline__ void unpack_half4(uint2 u, float2& a, float2& b) {
    a = __half22float2(*(__half2*)&u.x);
    b = __half22float2(*(__half2*)&u.y);
}

// init fp16 mirror of embeddings AND histogram+rank (fused).
__global__ void init_kernel(const float4* __restrict__ user4,
                            const float4* __restrict__ item4,
                            const int* __restrict__ rows, int nnz) {
    int i = blockIdx.x * blockDim.x + threadIdx.x;
    if (i < nnz) g_rank[i] = atomicAdd(&g_cnt[rows[i]], 1);
    if (i >= NF4) return;
    float4 v = (i < NUP1 * 16) ? __ldg(&user4[i])
                               : __ldg(&item4[i - NUP1 * 16 + 16]);
    g_A16[i] = pack_half4(make_float2(v.x, v.y), make_float2(v.z, v.w));
}

// Single-pass decoupled-lookback scan -> g_ptr; self-clears g_cnt.
__global__ void scan_kernel() {
    int t = threadIdx.x, b = blockIdx.x;
    int lane = t & 31, wid = t >> 5;
    int gid = b * SCAN_B + t;

    int cnt = (gid < NROWS) ? g_cnt[gid] : 0;

    int incl = cnt;
    #pragma unroll
    for (int o = 1; o < 32; o <<= 1) {
        int n = __shfl_up_sync(0xffffffffu, incl, o);
        if (lane >= o) incl += n;
    }
    __shared__ int wsum[32];
    __shared__ int s_excl;
    if (lane == 31) wsum[wid] = incl;
    __syncthreads();
    if (wid == 0) {
        int v = wsum[lane];
        #pragma unroll
        for (int o = 1; o < 32; o <<= 1) {
            int n = __shfl_up_sync(0xffffffffu, v, o);
            if (lane >= o) v += n;
        }
        wsum[lane] = v;
    }
    __syncthreads();
    int block_incl = incl + (wid ? wsum[wid - 1] : 0);
    int total = wsum[31];

    if (t == 0) {
        if (b == 0) { g_look[0] = (2ull << 32) | (unsigned)total; s_excl = 0; }
        else          g_look[b] = (1ull << 32) | (unsigned)total;
    }
    if (b > 0 && wid == 0) {
        int excl = 0;
        int idx = b - 1;
        while (true) {
            int look = idx - lane;
            unsigned long long w; int st;
            do {
                w = g_look[look < 0 ? 0 : look];
                st = (look < 0) ? 2 : (int)(w >> 32);
            } while (__any_sync(0xffffffffu, st == 0));
            int val = (look < 0) ? 0 : (int)(unsigned)w;
            unsigned pm = __ballot_sync(0xffffffffu, (look >= 0) && st == 2);
            int contrib;
            if (pm) {
                int plane = __ffs(pm) - 1;
                contrib = (lane <= plane) ? val : 0;
            } else {
                contrib = val;
            }
            #pragma unroll
            for (int o = 16; o; o >>= 1)
                contrib += __shfl_down_sync(0xffffffffu, contrib, o);
            contrib = __shfl_sync(0xffffffffu, contrib, 0);
            excl += contrib;
            if (pm) break;
            idx -= 32;
        }
        if (lane == 0) {
            g_look[b] = (2ull << 32) | (unsigned)(excl + total);
            s_excl = excl;
        }
    }
    __syncthreads();
    if (gid < NROWS) {
        int ex = s_excl + block_incl - cnt;
        g_ptr[gid] = ex;
        g_cnt[gid] = 0;                        // self-clean for next replay
        if (gid == NROWS - 1) g_ptr[NROWS] = ex + cnt;
    }
}

// Atomic-free bucket, 4 edges per thread (4 independent dep chains -> MLP 4).
// Also clears g_look.
__global__ void scatter_kernel(const int* __restrict__ rows,
                               const int* __restrict__ cols,
                               const float* __restrict__ vals,
                               int nnz, int T4) {
    int t = blockIdx.x * blockDim.x + threadIdx.x;
    if (t < NB) g_look[t] = 0ull;

    int e0 = t, e1 = t + T4, e2 = t + 2 * T4, e3 = t + 3 * T4;
    bool m0 = e0 < nnz, m1 = e1 < nnz, m2 = e2 < nnz, m3 = e3 < nnz;

    int r0 = m0 ? __ldg(&rows[e0]) : 0;
    int r1 = m1 ? __ldg(&rows[e1]) : 0;
    int r2 = m2 ? __ldg(&rows[e2]) : 0;
    int r3 = m3 ? __ldg(&rows[e3]) : 0;
    int k0 = m0 ? __ldg(&g_rank[e0]) : 0;
    int k1 = m1 ? __ldg(&g_rank[e1]) : 0;
    int k2 = m2 ? __ldg(&g_rank[e2]) : 0;
    int k3 = m3 ? __ldg(&g_rank[e3]) : 0;
    int c0 = m0 ? __ldg(&cols[e0]) : 0;
    int c1 = m1 ? __ldg(&cols[e1]) : 0;
    int c2 = m2 ? __ldg(&cols[e2]) : 0;
    int c3 = m3 ? __ldg(&cols[e3]) : 0;
    float v0 = m0 ? __ldg(&vals[e0]) : 0.f;
    float v1 = m1 ? __ldg(&vals[e1]) : 0.f;
    float v2 = m2 ? __ldg(&vals[e2]) : 0.f;
    float v3 = m3 ? __ldg(&vals[e3]) : 0.f;
    int p0 = m0 ? __ldg(&g_ptr[r0]) : 0;
    int p1 = m1 ? __ldg(&g_ptr[r1]) : 0;
    int p2 = m2 ? __ldg(&g_ptr[r2]) : 0;
    int p3 = m3 ? __ldg(&g_ptr[r3]) : 0;

    if (m0) g_edge[p0 + k0] = make_uint2((unsigned)c0, (unsigned)__float_as_int(v0));
    if (m1) g_edge[p1 + k1] = make_uint2((unsigned)c1, (unsigned)__float_as_int(v1));
    if (m2) g_edge[p2 + k2] = make_uint2((unsigned)c2, (unsigned)__float_as_int(v2));
    if (m3) g_edge[p3 + k3] = make_uint2((unsigned)c3, (unsigned)__float_as_int(v3));
}

// Half-warp per row: 16 lanes x half4 (8B) = one 128B row.
// fp16 gather, fp32 FFMA accumulation (R12 shape, unchanged).
__device__ __forceinline__ void row_spmv(const uint2* __restrict__ xl,
                                         int s, int e,
                                         float2& s0, float2& s1) {
    s0 = make_float2(0.f, 0.f);
    s1 = make_float2(0.f, 0.f);
    for (int j = s; j < e; j += 4) {
        uint2 e0 = __ldg(&g_edge[j]);
        uint2 e1 = (j + 1 < e) ? __ldg(&g_edge[j + 1]) : make_uint2(0u, 0u);
        uint2 e2 = (j + 2 < e) ? __ldg(&g_edge[j + 2]) : make_uint2(0u, 0u);
        uint2 e3 = (j + 3 < e) ? __ldg(&g_edge[j + 3]) : make_uint2(0u, 0u);
        uint2 g0 = __ldg(&xl[e0.x * 16u]);
        uint2 g1 = __ldg(&xl[e1.x * 16u]);
        uint2 g2 = __ldg(&xl[e2.x * 16u]);
        uint2 g3 = __ldg(&xl[e3.x * 16u]);
        float v0 = __uint_as_float(e0.y);
        float v1 = __uint_as_float(e1.y);
        float v2 = __uint_as_float(e2.y);
        float v3 = __uint_as_float(e3.y);
        float2 a, b;
        unpack_half4(g0, a, b);
        s0.x = fmaf(v0, a.x, s0.x); s0.y = fmaf(v0, a.y, s0.y);
        s1.x = fmaf(v0, b.x, s1.x); s1.y = fmaf(v0, b.y, s1.y);
        unpack_half4(g1, a, b);
        s0.x = fmaf(v1, a.x, s0.x); s0.y = fmaf(v1, a.y, s0.y);
        s1.x = fmaf(v1, b.x, s1.x); s1.y = fmaf(v1, b.y, s1.y);
        unpack_half4(g2, a, b);
        s0.x = fmaf(v2, a.x, s0.x); s0.y = fmaf(v2, a.y, s0.y);
        s1.x = fmaf(v2, b.x, s1.x); s1.y = fmaf(v2, b.y, s1.y);
        unpack_half4(g3, a, b);
        s0.x = fmaf(v3, a.x, s0.x); s0.y = fmaf(v3, a.y, s0.y);
        s1.x = fmaf(v3, b.x, s1.x); s1.y = fmaf(v3, b.y, s1.y);
    }
}

__global__ void spmm_mid(int layer) {
    int warp = (blockIdx.x * blockDim.x + threadIdx.x) >> 5;
    int lane = threadIdx.x & 31;
    int row  = warp * 2 + (lane >> 4);
    if (row >= NROWS) return;
    int l15 = lane & 15;
    const uint2* __restrict__ xl =
        ((layer == 0) ? g_A16 : g_B16) + l15;
    uint2* __restrict__ y = (layer == 0) ? g_B16 : g_C16;
    float2 s0, s1;
    row_spmv(xl, g_ptr[row], g_ptr[row + 1], s0, s1);
    y[(size_t)row * 16 + l15] = pack_half4(s0, s1);
}

__global__ void spmm_final(const float4* __restrict__ user4,
                           const float4* __restrict__ item4,
                           float4* __restrict__ out) {
    int warp = (blockIdx.x * blockDim.x + threadIdx.x) >> 5;
    int lane = threadIdx.x & 31;
    int row  = warp * 2 + (lane >> 4);
    if (row >= NROWS) return;
    int l15 = lane & 15;
    const uint2* __restrict__ xl = g_C16 + l15;
    float2 s0, s1;
    row_spmv(xl, g_ptr[row], g_ptr[row + 1], s0, s1);
    size_t o = (size_t)row * 16 + l15;
    float4 a = (row < NUP1) ? __ldg(&user4[o])
                            : __ldg(&item4[(size_t)(row - NUP1 + 1) * 16 + l15]);
    float2 b0, b1, c0, c1;
    unpack_half4(g_B16[o], b0, b1);
    unpack_half4(g_C16[o], c0, c1);
    int outrow = (row < NUP1) ? row : row + 1;
    out[(size_t)outrow * 16 + l15] =
        make_float4((a.x + b0.x + c0.x + s0.x) * 0.25f,
                    (a.y + b0.y + c0.y + s0.y) * 0.25f,
                    (a.z + b1.x + c1.x + s1.x) * 0.25f,
                    (a.w + b1.y + c1.y + s1.y) * 0.25f);
    if (row == 0)
        out[(size_t)NUP1 * 16 + l15] = make_float4(0.f, 0.f, 0.f, 0.f);
}

extern "C" void kernel_launch(void* const* d_in, const int* in_sizes, int n_in,
                              void* d_out, int out_size) {
    const float4* user4 = (const float4*)d_in[0];
    const float4* item4 = (const float4*)d_in[1];
    const int*    rows  = (const int*)d_in[2];
    const int*    cols  = (const int*)d_in[3];
    const float*  vals  = (const float*)d_in[4];
    float4*       out   = (float4*)d_out;

    const int nnz = in_sizes[2];
    const int TB = 256;

    const int gInit = (NF4 + TB - 1) / TB;     // NF4 > NNZE, covers both
    const int T4    = (nnz + 3) / 4;
    const int gScat = (T4 + TB - 1) / TB;
    const int nWarp = (NROWS + 1) / 2;
    const int gSpmm = (nWarp * 32 + TB - 1) / TB;

    init_kernel<<<gInit, TB>>>(user4, item4, rows, nnz);      // 0
    scan_kernel<<<NB, SCAN_B>>>();                            // 1
    scatter_kernel<<<gScat, TB>>>(rows, cols, vals, nnz, T4); // 2 (MLP 4)
    spmm_mid<<<gSpmm, TB>>>(0);                               // 3
    spmm_mid<<<gSpmm, TB>>>(1);                               // 4
    spmm_final<<<gSpmm, TB>>>(user4, item4, out);             // 5
}